// round 1
// baseline (speedup 1.0000x reference)
#include <cuda_runtime.h>
#include <cuda_bf16.h>

// ---------------------------------------------------------------------------
// GCN: out = GC2( relu( GC1(X) ) ),  GC(x) = D_in^{-1/2} A^T ( D_out^{-1/2} x ) W + b
// Reordered: Y = (x * rs_out) @ W  first, then CSR gather-sum, then * rs_in + b.
// ---------------------------------------------------------------------------

#define MAXN 10000
#define MAXE 640000

__device__ int    g_cnt_in [MAXN];
__device__ int    g_cnt_out[MAXN];
__device__ int    g_rowptr [MAXN + 1];
__device__ int    g_cursor [MAXN];
__device__ int    g_esrc   [MAXE];
__device__ float  g_rsin   [MAXN];
__device__ float  g_rsout  [MAXN];
__device__ float4 g_Y1     [MAXN * 32];   // 10000 x 128 f32
__device__ float4 g_H1     [MAXN * 32];   // 10000 x 128 f32
__device__ float4 g_Y2     [MAXN * 16];   // 10000 x 64  f32
__device__ int    g_is64;

// ---------------------------------------------------------------------------

__global__ void init_kernel(int nnodes) {
    int i = blockIdx.x * blockDim.x + threadIdx.x;
    if (i < nnodes) { g_cnt_in[i] = 0; g_cnt_out[i] = 0; }
    if (i == 0) g_is64 = 1;
}

// Detect whether index buffers are int64 or int32. If the data is int32, the
// int64 interpretation combines two random node ids; the high word is nonzero
// with prob ~1-1e-4 per sample, so 256 samples decide with certainty.
__global__ void detect_kernel(const void* __restrict__ src, int nedges) {
    int idx = (threadIdx.x * 37) % (nedges / 2);
    long long v = ((const long long*)src)[idx];
    if (v < 0 || v >= 1000000LL) atomicAnd(&g_is64, 0);
}

__device__ __forceinline__ int load_idx(const void* p, int e, int is64) {
    return is64 ? (int)((const long long*)p)[e] : ((const int*)p)[e];
}

__global__ void hist_kernel(const void* __restrict__ src, const void* __restrict__ dst,
                            int nedges) {
    int is64 = g_is64;
    for (int e = blockIdx.x * blockDim.x + threadIdx.x; e < nedges;
         e += gridDim.x * blockDim.x) {
        atomicAdd(&g_cnt_out[load_idx(src, e, is64)], 1);
        atomicAdd(&g_cnt_in [load_idx(dst, e, is64)], 1);
    }
}

// Single-block exclusive scan of g_cnt_in -> g_rowptr (+cursor), plus rsqrt norms.
__global__ void scan_kernel(int nnodes) {
    __shared__ int sdata[1024];
    int t = threadIdx.x;
    int per = (nnodes + (int)blockDim.x - 1) / (int)blockDim.x;   // 10
    int base = t * per;
    int sum = 0;
    for (int i = 0; i < per; ++i) {
        int idx = base + i;
        if (idx < nnodes) sum += g_cnt_in[idx];
    }
    sdata[t] = sum;
    __syncthreads();
    for (int off = 1; off < (int)blockDim.x; off <<= 1) {
        int v = (t >= off) ? sdata[t - off] : 0;
        __syncthreads();
        sdata[t] += v;
        __syncthreads();
    }
    int run = (t == 0) ? 0 : sdata[t - 1];
    for (int i = 0; i < per; ++i) {
        int idx = base + i;
        if (idx < nnodes) {
            g_rowptr[idx] = run;
            g_cursor[idx] = run;
            int ci = g_cnt_in[idx];
            run += ci;
            int co = g_cnt_out[idx];
            g_rsin [idx] = rsqrtf((float)(ci > 1 ? ci : 1));
            g_rsout[idx] = rsqrtf((float)(co > 1 ? co : 1));
        }
    }
    if (t == (int)blockDim.x - 1) g_rowptr[nnodes] = sdata[blockDim.x - 1];
}

__global__ void scatter_kernel(const void* __restrict__ src, const void* __restrict__ dst,
                               int nedges) {
    int is64 = g_is64;
    for (int e = blockIdx.x * blockDim.x + threadIdx.x; e < nedges;
         e += gridDim.x * blockDim.x) {
        int s = load_idx(src, e, is64);
        int d = load_idx(dst, e, is64);
        int pos = atomicAdd(&g_cursor[d], 1);
        g_esrc[pos] = s;
    }
}

// ---------------------------------------------------------------------------
// Dense GEMM: Y[r][c] = sum_k (X[r][k] * scale[r]) * W[k][c]
// LAYER 1: X=in_feat, scale=g_rsout, Y=g_Y1, 128 cols (two 64-row k-chunks of W in smem)
// LAYER 2: X=g_H1 (scale prefolded), Y=g_Y2, 64 cols (whole W in smem)
// 8 warps/block, 4 rows/warp register blocking: each smem W read feeds 4 FMAs.
// ---------------------------------------------------------------------------
template <int LAYER>
__global__ void __launch_bounds__(256) gemm_kernel(const float* __restrict__ Xext,
                                                   const float* __restrict__ W,
                                                   int nrows) {
    constexpr int NCOLS = (LAYER == 1) ? 128 : 64;
    constexpr int KC    = (LAYER == 1) ? 64  : 128;
    constexpr int NCH   = 128 / KC;
    constexpr int Q     = NCOLS / 32;
    constexpr int RPW   = 4;
    constexpr int RPB   = RPW * 8;   // 32 rows per block-iter

    __shared__ float Ws[KC * NCOLS];   // 32 KB

    const float* X = (LAYER == 1) ? Xext : (const float*)g_H1;
    float*       Y = (LAYER == 1) ? (float*)g_Y1 : (float*)g_Y2;

    int warp = threadIdx.x >> 5, lane = threadIdx.x & 31;

    for (int ch = 0; ch < NCH; ++ch) {
        for (int i = threadIdx.x; i < KC * NCOLS; i += blockDim.x) {
            int kk = i / NCOLS, cc = i % NCOLS;
            Ws[i] = W[(ch * KC + kk) * NCOLS + cc];
        }
        __syncthreads();

        for (int rbase = blockIdx.x * RPB + warp * RPW; rbase < nrows;
             rbase += gridDim.x * RPB) {
            float acc[RPW][Q];
#pragma unroll
            for (int r = 0; r < RPW; ++r)
#pragma unroll
                for (int q = 0; q < Q; ++q) acc[r][q] = 0.f;

            for (int kb = 0; kb < KC; kb += 32) {
                float xv[RPW];
#pragma unroll
                for (int r = 0; r < RPW; ++r) {
                    int row = rbase + r;
                    float v = 0.f;
                    if (row < nrows) {
                        v = X[row * 128 + ch * KC + kb + lane];
                        if (LAYER == 1) v *= g_rsout[row];
                    }
                    xv[r] = v;
                }
#pragma unroll
                for (int j = 0; j < 32; ++j) {
                    float a[RPW];
#pragma unroll
                    for (int r = 0; r < RPW; ++r)
                        a[r] = __shfl_sync(0xffffffffu, xv[r], j);
#pragma unroll
                    for (int q = 0; q < Q; ++q) {
                        float w = Ws[(kb + j) * NCOLS + lane + 32 * q];
#pragma unroll
                        for (int r = 0; r < RPW; ++r)
                            acc[r][q] = fmaf(a[r], w, acc[r][q]);
                    }
                }
            }
#pragma unroll
            for (int r = 0; r < RPW; ++r) {
                int row = rbase + r;
                if (row >= nrows) break;
#pragma unroll
                for (int q = 0; q < Q; ++q) {
                    int c = lane + 32 * q;
                    if (NCH == 1 || ch == 0) Y[row * NCOLS + c] = acc[r][q];
                    else                     Y[row * NCOLS + c] += acc[r][q];
                }
            }
        }
        __syncthreads();
    }
}

// ---------------------------------------------------------------------------
// CSR gather SpMM + fused epilogue.
// LAYER 1: in=g_Y1 (128 f), out=g_H1 = relu(sum*rs_in + b1) * rs_out
// LAYER 2: in=g_Y2 (64 f),  out=d_out = sum*rs_in + b2
// One float4 column-chunk per thread; 32 (or 16) consecutive lanes per node ->
// each edge's gather is one fully-coalesced 512B (256B) read from L2-resident Y.
// ---------------------------------------------------------------------------
template <int LAYER>
__global__ void __launch_bounds__(256) spmm_kernel(const float* __restrict__ bias,
                                                   float* __restrict__ outext,
                                                   int nnodes) {
    constexpr int F   = (LAYER == 1) ? 128 : 64;
    constexpr int LPN = F / 4;   // float4 chunks per node

    const float4* Yin = (LAYER == 1) ? (const float4*)g_Y1 : (const float4*)g_Y2;
    float4*       out = (LAYER == 1) ? (float4*)g_H1 : (float4*)outext;

    int gid  = blockIdx.x * blockDim.x + threadIdx.x;
    int node = gid / LPN;
    int c    = gid % LPN;
    if (node >= nnodes) return;

    int beg = g_rowptr[node];
    int end = g_rowptr[node + 1];

    float4 acc = make_float4(0.f, 0.f, 0.f, 0.f);
    int e = beg;
    for (; e + 3 < end; e += 4) {
        int s0 = g_esrc[e], s1 = g_esrc[e + 1], s2 = g_esrc[e + 2], s3 = g_esrc[e + 3];
        float4 v0 = Yin[s0 * LPN + c];
        float4 v1 = Yin[s1 * LPN + c];
        float4 v2 = Yin[s2 * LPN + c];
        float4 v3 = Yin[s3 * LPN + c];
        v0.x += v1.x; v0.y += v1.y; v0.z += v1.z; v0.w += v1.w;
        v2.x += v3.x; v2.y += v3.y; v2.z += v3.z; v2.w += v3.w;
        acc.x += v0.x + v2.x; acc.y += v0.y + v2.y;
        acc.z += v0.z + v2.z; acc.w += v0.w + v2.w;
    }
    for (; e < end; ++e) {
        int s = g_esrc[e];
        float4 v = Yin[s * LPN + c];
        acc.x += v.x; acc.y += v.y; acc.z += v.z; acc.w += v.w;
    }

    float  ri = g_rsin[node];
    float4 b  = ((const float4*)bias)[c];
    float4 r;
    r.x = fmaf(acc.x, ri, b.x);
    r.y = fmaf(acc.y, ri, b.y);
    r.z = fmaf(acc.z, ri, b.z);
    r.w = fmaf(acc.w, ri, b.w);
    if (LAYER == 1) {
        float ro = g_rsout[node];
        r.x = fmaxf(r.x, 0.f) * ro;
        r.y = fmaxf(r.y, 0.f) * ro;
        r.z = fmaxf(r.z, 0.f) * ro;
        r.w = fmaxf(r.w, 0.f) * ro;
    }
    out[node * LPN + c] = r;
}

// ---------------------------------------------------------------------------

extern "C" void kernel_launch(void* const* d_in, const int* in_sizes, int n_in,
                              void* d_out, int out_size) {
    const float* in_feat = (const float*)d_in[0];
    const void*  src     = d_in[1];
    const void*  dst     = d_in[2];
    const float* W1      = (const float*)d_in[3];
    const float* b1      = (const float*)d_in[4];
    const float* W2      = (const float*)d_in[5];
    const float* b2      = (const float*)d_in[6];

    int nnodes = in_sizes[0] / 128;   // 10000
    int nedges = in_sizes[1];         // 640000

    const int TB = 256;

    init_kernel<<<(nnodes + TB - 1) / TB, TB>>>(nnodes);
    detect_kernel<<<1, 256>>>(src, nedges);
    hist_kernel<<<240, TB>>>(src, dst, nedges);
    scan_kernel<<<1, 1024>>>(nnodes);
    scatter_kernel<<<240, TB>>>(src, dst, nedges);

    int gemm_blocks = (nnodes + 31) / 32;
    gemm_kernel<1><<<gemm_blocks, 256>>>(in_feat, W1, nnodes);
    spmm_kernel<1><<<(nnodes * 32 + TB - 1) / TB, TB>>>(b1, nullptr, nnodes);
    gemm_kernel<2><<<gemm_blocks, 256>>>(nullptr, W2, nnodes);
    spmm_kernel<2><<<(nnodes * 16 + TB - 1) / TB, TB>>>(b2, (float*)d_out, nnodes);
}